// round 11
// baseline (speedup 1.0000x reference)
#include <cuda_runtime.h>
#include <cuda_fp16.h>
#include <cstdint>

#define HCH  512
#define LSEQ 4096
#define TAPS 64

#define NT     256              // 8 warps
#define NTILE  4
#define CHUNK  512              // 4 seq-tiles of 128 per chunk
#define NCHUNK 4
#define TCTA   (CHUNK * NCHUNK) // 2048 t per CTA
#define STRW   292              // u32 words per strip (288 used + 4 pad), 292%32==4

__device__ __forceinline__ uint32_t pk_h2(float a, float b) {
    __half2 t = __floats2half2_rn(a, b);
    return *reinterpret_cast<uint32_t*>(&t);
}
__device__ __forceinline__ uint32_t smem_u32(const void* p) {
    uint32_t a;
    asm("{ .reg .u64 t; cvta.to.shared.u64 t, %1; cvt.u32.u64 %0, t; }" : "=r"(a) : "l"(p));
    return a;
}
__device__ __forceinline__ void mma_f16(float* d, uint32_t a0, uint32_t a1,
                                        uint32_t a2, uint32_t a3,
                                        uint32_t b0, uint32_t b1) {
    asm volatile(
        "mma.sync.aligned.m16n8k16.row.col.f32.f16.f16.f32 "
        "{%0,%1,%2,%3}, {%4,%5,%6,%7}, {%8,%9}, {%0,%1,%2,%3};"
        : "+f"(d[0]), "+f"(d[1]), "+f"(d[2]), "+f"(d[3])
        : "r"(a0), "r"(a1), "r"(a2), "r"(a3), "r"(b0), "r"(b1));
}
__device__ __forceinline__ void ldsm_x4(uint32_t& r0, uint32_t& r1,
                                        uint32_t& r2, uint32_t& r3, uint32_t addr) {
    asm volatile("ldmatrix.sync.aligned.m8n8.x4.shared.b16 {%0,%1,%2,%3}, [%4];"
                 : "=r"(r0), "=r"(r1), "=r"(r2), "=r"(r3) : "r"(addr));
}

__global__ __launch_bounds__(NT, 3) void conv_mma(const float* __restrict__ up,
                                                  const float* __restrict__ Bp,
                                                  const float* __restrict__ Cp,
                                                  const float* __restrict__ Dp,
                                                  float* __restrict__ yp) {
    __shared__ alignas(16) uint32_t sBuf[2][8 * STRW];   // double-buffered strips
    __shared__ float    sK[TAPS];
    __shared__ uint32_t sTab[5 * 3 * 32];

    const int tid  = threadIdx.x;
    const int wid  = tid >> 5;
    const int lane = tid & 31;
    const int h    = blockIdx.y;
    const int t0   = blockIdx.x * TCTA;

    const float* uh = up + (size_t)h * LSEQ;
    float*       yh = yp + (size_t)h * LSEQ;
    const size_t bstr = (size_t)HCH * LSEQ;

    // per-thread im2col slot (fixed across chunks): idx = tid + it*NT
    // it=0,1 always valid; it=2 valid iff tid < 64
    const int i0b = tid / 72,         i0q = tid - i0b * 72;
    const int i1b = (tid + 256) / 72, i1q = (tid + 256) - i1b * 72;
    const int i2b = (tid + 512) / 72, i2q = (tid + 512) - i2b * 72;
    const bool v2 = tid < 64;

    float4 p00, p01, p10, p11, p20, p21;   // prefetch registers

    #define PREFETCH(tc0)                                                     \
    {                                                                         \
        int t;                                                                \
        t = (tc0) - 64 + i0q * 8;                                             \
        p00 = make_float4(0.f,0.f,0.f,0.f); p01 = p00;                        \
        if (t >= 0) { const float* p = uh + (size_t)i0b * bstr + t;           \
            p00 = *reinterpret_cast<const float4*>(p);                        \
            p01 = *reinterpret_cast<const float4*>(p + 4); }                  \
        t = (tc0) - 64 + i1q * 8;                                             \
        p10 = make_float4(0.f,0.f,0.f,0.f); p11 = p10;                        \
        if (t >= 0) { const float* p = uh + (size_t)i1b * bstr + t;           \
            p10 = *reinterpret_cast<const float4*>(p);                        \
            p11 = *reinterpret_cast<const float4*>(p + 4); }                  \
        p20 = make_float4(0.f,0.f,0.f,0.f); p21 = p20;                        \
        if (v2) { t = (tc0) - 64 + i2q * 8;                                   \
            if (t >= 0) { const float* p = uh + (size_t)i2b * bstr + t;       \
                p20 = *reinterpret_cast<const float4*>(p);                    \
                p21 = *reinterpret_cast<const float4*>(p + 4); } }            \
    }

    #define STORE_STRIPS(buf)                                                 \
    {                                                                         \
        uint4 w;                                                              \
        w.x = pk_h2(p00.x, p00.y); w.y = pk_h2(p00.z, p00.w);                 \
        w.z = pk_h2(p01.x, p01.y); w.w = pk_h2(p01.z, p01.w);                 \
        *reinterpret_cast<uint4*>(sBuf[buf] + i0b * STRW + i0q * 4) = w;      \
        w.x = pk_h2(p10.x, p10.y); w.y = pk_h2(p10.z, p10.w);                 \
        w.z = pk_h2(p11.x, p11.y); w.w = pk_h2(p11.z, p11.w);                 \
        *reinterpret_cast<uint4*>(sBuf[buf] + i1b * STRW + i1q * 4) = w;      \
        if (v2) {                                                             \
            w.x = pk_h2(p20.x, p20.y); w.y = pk_h2(p20.z, p20.w);             \
            w.z = pk_h2(p21.x, p21.y); w.w = pk_h2(p21.z, p21.w);             \
            *reinterpret_cast<uint4*>(sBuf[buf] + i2b * STRW + i2q * 4) = w;  \
        }                                                                     \
    }

    // ---- chunk-0 prefetch first (longest latency) ----
    PREFETCH(t0)

    // ---- warps 0-1: K build + A-frag table (overlaps prefetch in warps 2-7) ----
    if (tid < 64) {
        {
            const float* Bh = Bp + h * TAPS;
            const float* Ch = Cp + h * TAPS;
            float a = (tid == 0) ? Dp[h] : 0.0f;
            #pragma unroll
            for (int j = 0; j < TAPS; ++j)
                if (j + tid < TAPS) a = fmaf(Bh[j], Ch[j + tid], a);
            sK[tid] = a;
        }
        asm volatile("bar.sync 1, 64;" ::: "memory");
        #pragma unroll
        for (int it = 0; it < 8; ++it) {
            int widx = tid + it * 64;
            if (widx < 480) {
                int l = widx & 31, dw = widx >> 5;
                int d = dw / 3, w = dw - d * 3;
                int s0 = 64 - 16 * d + (l >> 2) - ((l & 3) << 1);
                int sa = s0 + ((w == 1) ? 8 : (w == 2) ? -8 : 0);
                float fa = ((unsigned)sa < TAPS) ? sK[sa] : 0.0f;
                float fb = ((unsigned)(sa - 1) < TAPS) ? sK[sa - 1] : 0.0f;
                sTab[widx] = pk_h2(fa, fb);
            }
        }
    }
    __syncthreads();

    // A fragments: 15 conflict-free LDS.32
    uint32_t fh[5][3];
    #pragma unroll
    for (int d = 0; d < 5; ++d)
        #pragma unroll
        for (int w = 0; w < 3; ++w)
            fh[d][w] = sTab[(d * 3 + w) * 32 + lane];

    STORE_STRIPS(0)
    __syncthreads();

    const int jb = wid;
    const uint32_t ldm0 = smem_u32(sBuf) +
        (((lane & 7) * STRW) + (((lane >> 3) & 1) * 4) + (((lane >> 4) & 1) * 64)) * 4;
    const int j  = jb * 16 + (lane >> 2);
    const int nn = (lane & 3) * 2;

    #pragma unroll
    for (int c = 0; c < NCHUNK; ++c) {
        if (c < NCHUNK - 1) PREFETCH(t0 + (c + 1) * CHUNK)

        float acc[NTILE][4];
        #pragma unroll
        for (int tl = 0; tl < NTILE; ++tl)
            #pragma unroll
            for (int q = 0; q < 4; ++q) acc[tl][q] = 0.0f;

        const uint32_t ldm_base = ldm0 + (c & 1) * (8 * STRW * 4);
        #pragma unroll
        for (int d = 0; d < 5; ++d) {
            #pragma unroll
            for (int tp = 0; tp < 2; ++tp) {
                uint32_t b00, b01, b10, b11;
                ldsm_x4(b00, b01, b10, b11, ldm_base + ((jb + d) * 8 + tp * 128) * 4);
                mma_f16(acc[2*tp],   fh[d][0], fh[d][1], fh[d][2], fh[d][0], b00, b01);
                mma_f16(acc[2*tp+1], fh[d][0], fh[d][1], fh[d][2], fh[d][0], b10, b11);
            }
        }

        if (c < NCHUNK - 1) STORE_STRIPS((c + 1) & 1)

        // direct epilogue for chunk c
        {
            float* p0 = yh + (size_t)nn * bstr + t0 + c * CHUNK + j;
            #pragma unroll
            for (int tl = 0; tl < NTILE; ++tl) {
                float* q0 = p0 + tl * 128;
                float* q1 = q0 + bstr;
                q0[0] = acc[tl][0];
                q1[0] = acc[tl][1];
                q0[8] = acc[tl][2];
                q1[8] = acc[tl][3];
            }
        }

        if (c < NCHUNK - 1) __syncthreads();
    }
    #undef PREFETCH
    #undef STORE_STRIPS
}

extern "C" void kernel_launch(void* const* d_in, const int* in_sizes, int n_in,
                              void* d_out, int out_size) {
    const float* u = (const float*)d_in[0];   // (8, 512, 4096)
    const float* B = (const float*)d_in[1];   // (512, 64)
    const float* C = (const float*)d_in[2];   // (1, 512, 64)
    const float* D = (const float*)d_in[3];   // (512,)
    float* y = (float*)d_out;                 // (8, 512, 4096)

    dim3 grid(LSEQ / TCTA, HCH);              // (2, 512) = 1024 CTAs
    conv_mma<<<grid, NT>>>(u, B, C, D, y);
}

// round 12
// speedup vs baseline: 1.1858x; 1.1858x over previous
#include <cuda_runtime.h>
#include <cuda_fp16.h>
#include <cstdint>

#define HCH  512
#define LSEQ 4096
#define TAPS 64

#define NT    256               // 8 warps
#define NTILE 4
#define TCTA  512               // 4 seq-tiles of 128 per CTA
#define STRW  292               // u32 words per batch strip (288 used + 4 pad), 292%32==4

__device__ __forceinline__ uint32_t pk_h2(float a, float b) {
    __half2 t = __floats2half2_rn(a, b);
    return *reinterpret_cast<uint32_t*>(&t);
}
__device__ __forceinline__ uint32_t smem_u32(const void* p) {
    uint32_t a;
    asm("{ .reg .u64 t; cvta.to.shared.u64 t, %1; cvt.u32.u64 %0, t; }" : "=r"(a) : "l"(p));
    return a;
}
__device__ __forceinline__ void mma_f16(float* d, uint32_t a0, uint32_t a1,
                                        uint32_t a2, uint32_t a3,
                                        uint32_t b0, uint32_t b1) {
    asm volatile(
        "mma.sync.aligned.m16n8k16.row.col.f32.f16.f16.f32 "
        "{%0,%1,%2,%3}, {%4,%5,%6,%7}, {%8,%9}, {%0,%1,%2,%3};"
        : "+f"(d[0]), "+f"(d[1]), "+f"(d[2]), "+f"(d[3])
        : "r"(a0), "r"(a1), "r"(a2), "r"(a3), "r"(b0), "r"(b1));
}
__device__ __forceinline__ void ldsm_x4(uint32_t& r0, uint32_t& r1,
                                        uint32_t& r2, uint32_t& r3, uint32_t addr) {
    asm volatile("ldmatrix.sync.aligned.m8n8.x4.shared.b16 {%0,%1,%2,%3}, [%4];"
                 : "=r"(r0), "=r"(r1), "=r"(r2), "=r"(r3) : "r"(addr));
}

__global__ __launch_bounds__(NT, 4) void conv_mma(const float* __restrict__ up,
                                                  const float* __restrict__ Bp,
                                                  const float* __restrict__ Cp,
                                                  const float* __restrict__ Dp,
                                                  float* __restrict__ yp) {
    __shared__ alignas(16) uint32_t sBuf[8 * STRW];      // 8 fp16 batch strips
    __shared__ alignas(16) float sBC[128];               // staged B | C (64 + 64)
    __shared__ float    sK[TAPS];
    __shared__ uint32_t sTab[5 * 3 * 32];                // A-frag words [d][w][lane]

    const int tid  = threadIdx.x;
    const int wid  = tid >> 5;
    const int lane = tid & 31;
    const int h    = blockIdx.y;
    const int t0   = blockIdx.x * TCTA;

    const float* uh = up + (size_t)h * LSEQ;
    float*       yh = yp + (size_t)h * LSEQ;
    const size_t bstr = (size_t)HCH * LSEQ;

    if (tid < 64) {
        // ---- warps 0-1: stage B,C; 64-tap correlation; A-frag table ----
        if (tid < 32) {
            int l = tid & 15;
            const float* src = (tid < 16) ? (Bp + h * TAPS) : (Cp + h * TAPS);
            reinterpret_cast<float4*>(sBC)[(tid < 16 ? 0 : 16) + l] =
                reinterpret_cast<const float4*>(src)[l];
        }
        asm volatile("bar.sync 1, 64;" ::: "memory");

        {   // K[s] = sum_j B[j]*C[j+s], K[0] += D[h]
            const int s = tid;
            float a = (s == 0) ? Dp[h] : 0.0f;
            #pragma unroll
            for (int j = 0; j < TAPS; ++j)
                if (j + s < TAPS) a = fmaf(sBC[j], sBC[64 + j + s], a);
            sK[s] = a;
        }
        asm volatile("bar.sync 1, 64;" ::: "memory");

        // A-frag table (480 warp-invariant words)
        #pragma unroll
        for (int it = 0; it < 8; ++it) {
            int widx = tid + it * 64;
            if (widx < 480) {
                int l = widx & 31, dw = widx >> 5;
                int d = dw / 3, w = dw - d * 3;
                int s0 = 64 - 16 * d + (l >> 2) - ((l & 3) << 1);
                int sa = s0 + ((w == 1) ? 8 : (w == 2) ? -8 : 0);
                float fa = ((unsigned)sa < TAPS) ? sK[sa] : 0.0f;
                float fb = ((unsigned)(sa - 1) < TAPS) ? sK[sa - 1] : 0.0f;
                sTab[widx] = pk_h2(fa, fb);
            }
        }
    } else {
        // ---- warps 2-7: im2col, 8 strips of 576 floats (t in [t0-64, t0+512)) ----
        #pragma unroll
        for (int it = 0; it < 3; ++it) {
            int idx = (tid - 64) + it * 192;             // 0..575, exact
            int b = idx / 72, q8 = idx - b * 72;
            int t = t0 - 64 + q8 * 8;
            float4 v0 = make_float4(0.f, 0.f, 0.f, 0.f);
            float4 v1 = v0;
            if (t >= 0) {
                const float* p = uh + (size_t)b * bstr + t;
                v0 = *reinterpret_cast<const float4*>(p);
                v1 = *reinterpret_cast<const float4*>(p + 4);
            }
            uint4 w;
            w.x = pk_h2(v0.x, v0.y); w.y = pk_h2(v0.z, v0.w);
            w.z = pk_h2(v1.x, v1.y); w.w = pk_h2(v1.z, v1.w);
            *reinterpret_cast<uint4*>(sBuf + b * STRW + q8 * 4) = w;
        }
    }
    __syncthreads();

    // ---- per-warp A fragments: 15 conflict-free LDS.32 ----
    uint32_t fh[5][3];
    #pragma unroll
    for (int d = 0; d < 5; ++d)
        #pragma unroll
        for (int w = 0; w < 3; ++w)
            fh[d][w] = sTab[(d * 3 + w) * 32 + lane];

    // ---- Banded GEMM: warp wid -> row block jb; ldmatrix.x4 covers 2 tiles ----
    const int jb = wid;
    const uint32_t ldm_base = smem_u32(sBuf) +
        (((lane & 7) * STRW) + (((lane >> 3) & 1) * 4) + (((lane >> 4) & 1) * 64)) * 4;

    float acc[NTILE][4];
    #pragma unroll
    for (int tl = 0; tl < NTILE; ++tl)
        #pragma unroll
        for (int q = 0; q < 4; ++q) acc[tl][q] = 0.0f;

    #pragma unroll
    for (int d = 0; d < 5; ++d) {
        #pragma unroll
        for (int tp = 0; tp < 2; ++tp) {                 // tile pairs (0,1), (2,3)
            uint32_t b00, b01, b10, b11;
            ldsm_x4(b00, b01, b10, b11, ldm_base + ((jb + d) * 8 + tp * 128) * 4);
            mma_f16(acc[2 * tp],     fh[d][0], fh[d][1], fh[d][2], fh[d][0], b00, b01);
            mma_f16(acc[2 * tp + 1], fh[d][0], fh[d][1], fh[d][2], fh[d][0], b10, b11);
        }
    }

    // ---- Direct epilogue: streaming stores (y is write-once) ----
    {
        const int j  = jb * 16 + (lane >> 2);
        const int nn = (lane & 3) * 2;
        float* p0 = yh + (size_t)nn * bstr + t0 + j;
        #pragma unroll
        for (int tl = 0; tl < NTILE; ++tl) {
            float* q0 = p0 + tl * 128;
            float* q1 = q0 + bstr;
            __stcs(q0,     acc[tl][0]);
            __stcs(q1,     acc[tl][1]);
            __stcs(q0 + 8, acc[tl][2]);
            __stcs(q1 + 8, acc[tl][3]);
        }
    }
}

extern "C" void kernel_launch(void* const* d_in, const int* in_sizes, int n_in,
                              void* d_out, int out_size) {
    const float* u = (const float*)d_in[0];   // (8, 512, 4096)
    const float* B = (const float*)d_in[1];   // (512, 64)
    const float* C = (const float*)d_in[2];   // (1, 512, 64)
    const float* D = (const float*)d_in[3];   // (512,)
    float* y = (float*)d_out;                 // (8, 512, 4096)

    dim3 grid(LSEQ / TCTA, HCH);              // (8, 512) = 4096 CTAs
    conv_mma<<<grid, NT>>>(u, B, C, D, y);
}

// round 13
// speedup vs baseline: 1.2636x; 1.0656x over previous
#include <cuda_runtime.h>
#include <cuda_fp16.h>
#include <cstdint>

#define HCH  512
#define LSEQ 4096
#define TAPS 64

#define NT    256               // 8 warps
#define TCTA  512               // 4 seq-tiles of 128 per CTA
#define STRW  292               // u32 words per batch strip (288 used + 4 pad), 292%32==4

__device__ __forceinline__ uint32_t pk_h2(float a, float b) {
    __half2 t = __floats2half2_rn(a, b);
    return *reinterpret_cast<uint32_t*>(&t);
}
__device__ __forceinline__ uint32_t smem_u32(const void* p) {
    uint32_t a;
    asm("{ .reg .u64 t; cvta.to.shared.u64 t, %1; cvt.u32.u64 %0, t; }" : "=r"(a) : "l"(p));
    return a;
}
__device__ __forceinline__ void mma_f16(float* d, uint32_t a0, uint32_t a1,
                                        uint32_t a2, uint32_t a3,
                                        uint32_t b0, uint32_t b1) {
    asm volatile(
        "mma.sync.aligned.m16n8k16.row.col.f32.f16.f16.f32 "
        "{%0,%1,%2,%3}, {%4,%5,%6,%7}, {%8,%9}, {%0,%1,%2,%3};"
        : "+f"(d[0]), "+f"(d[1]), "+f"(d[2]), "+f"(d[3])
        : "r"(a0), "r"(a1), "r"(a2), "r"(a3), "r"(b0), "r"(b1));
}
__device__ __forceinline__ void ldsm_x4(uint32_t& r0, uint32_t& r1,
                                        uint32_t& r2, uint32_t& r3, uint32_t addr) {
    asm volatile("ldmatrix.sync.aligned.m8n8.x4.shared.b16 {%0,%1,%2,%3}, [%4];"
                 : "=r"(r0), "=r"(r1), "=r"(r2), "=r"(r3) : "r"(addr));
}

__global__ __launch_bounds__(NT, 4) void conv_mma(const float* __restrict__ up,
                                                  const float* __restrict__ Bp,
                                                  const float* __restrict__ Cp,
                                                  const float* __restrict__ Dp,
                                                  float* __restrict__ yp) {
    __shared__ alignas(16) uint32_t sBuf[8 * STRW];      // 8 fp16 batch strips
    __shared__ alignas(16) float sBC[128];               // staged B | C (64 + 64)
    __shared__ float    sK[TAPS];
    __shared__ uint32_t sTab[5 * 3 * 32];                // A-frag words [d][w][lane]

    const int tid  = threadIdx.x;
    const int wid  = tid >> 5;
    const int lane = tid & 31;
    const int h    = blockIdx.y;
    const int t0   = blockIdx.x * TCTA;

    const float* uh = up + (size_t)h * LSEQ;
    float*       yh = yp + (size_t)h * LSEQ;
    const size_t bstr = (size_t)HCH * LSEQ;

    if (tid < 64) {
        // ---- warps 0-1: stage B,C; 64-tap correlation; A-frag table ----
        if (tid < 32) {
            int l = tid & 15;
            const float* src = (tid < 16) ? (Bp + h * TAPS) : (Cp + h * TAPS);
            reinterpret_cast<float4*>(sBC)[(tid < 16 ? 0 : 16) + l] =
                reinterpret_cast<const float4*>(src)[l];
        }
        asm volatile("bar.sync 1, 64;" ::: "memory");

        {   // K[s] = sum_j B[j]*C[j+s], K[0] += D[h]
            const int s = tid;
            float a = (s == 0) ? Dp[h] : 0.0f;
            #pragma unroll
            for (int j = 0; j < TAPS; ++j)
                if (j + s < TAPS) a = fmaf(sBC[j], sBC[64 + j + s], a);
            sK[s] = a;
        }
        asm volatile("bar.sync 1, 64;" ::: "memory");

        // A-frag table (480 warp-invariant words)
        #pragma unroll
        for (int it = 0; it < 8; ++it) {
            int widx = tid + it * 64;
            if (widx < 480) {
                int l = widx & 31, dw = widx >> 5;
                int d = dw / 3, w = dw - d * 3;
                int s0 = 64 - 16 * d + (l >> 2) - ((l & 3) << 1);
                int sa = s0 + ((w == 1) ? 8 : (w == 2) ? -8 : 0);
                float fa = ((unsigned)sa < TAPS) ? sK[sa] : 0.0f;
                float fb = ((unsigned)(sa - 1) < TAPS) ? sK[sa - 1] : 0.0f;
                sTab[widx] = pk_h2(fa, fb);
            }
        }
    } else {
        // ---- warps 2-7: im2col, 8 strips of 576 floats (t in [t0-64, t0+512)) ----
        #pragma unroll
        for (int it = 0; it < 3; ++it) {
            int idx = (tid - 64) + it * 192;             // 0..575, exact
            int b = idx / 72, q8 = idx - b * 72;
            int t = t0 - 64 + q8 * 8;
            float4 v0 = make_float4(0.f, 0.f, 0.f, 0.f);
            float4 v1 = v0;
            if (t >= 0) {
                const float* p = uh + (size_t)b * bstr + t;
                v0 = *reinterpret_cast<const float4*>(p);
                v1 = *reinterpret_cast<const float4*>(p + 4);
            }
            uint4 w;
            w.x = pk_h2(v0.x, v0.y); w.y = pk_h2(v0.z, v0.w);
            w.z = pk_h2(v1.x, v1.y); w.w = pk_h2(v1.z, v1.w);
            *reinterpret_cast<uint4*>(sBuf + b * STRW + q8 * 4) = w;
        }
    }
    __syncthreads();

    // ---- per-warp A fragments: 15 conflict-free LDS.32 (depend on d only) ----
    uint32_t fh[5][3];
    #pragma unroll
    for (int d = 0; d < 5; ++d)
        #pragma unroll
        for (int w = 0; w < 3; ++w)
            fh[d][w] = sTab[(d * 3 + w) * 32 + lane];

    // ---- Banded GEMM: warp (tile = wid>>1, q = wid&1) owns row blocks 4q..4q+3
    //      of one tile; its k-window is k-blocks 4q..4q+7 -> only 4 ldsm.x4 ----
    const int tile = wid >> 1;
    const int q    = wid & 1;
    // ldsm lane groups g=lane>>3: g0 -> (kb 2s, k0-7), g1 -> (kb 2s, k8-15),
    //                             g2 -> (kb 2s+1, k0-7), g3 -> (kb 2s+1, k8-15)
    const uint32_t ldm0 = smem_u32(sBuf) +
        (((lane & 7) * STRW) + tile * 64 + (((lane >> 4) & 1) * 8) +
         (((lane >> 3) & 1) * 4)) * 4;

    float acc[4][4];
    #pragma unroll
    for (int i = 0; i < 4; ++i)
        #pragma unroll
        for (int r = 0; r < 4; ++r) acc[i][r] = 0.0f;

    #pragma unroll
    for (int s = 0; s < 4; ++s) {
        uint32_t b0, b1, b2, b3;                         // kb 2s (k0,k1), kb 2s+1 (k0,k1)
        ldsm_x4(b0, b1, b2, b3, ldm0 + ((4 * q + 2 * s) * 8) * 4);
        #pragma unroll
        for (int i = 0; i < 4; ++i) {
            const int de = 2 * s - i;                    // uses kb 2s
            const int do_ = 2 * s + 1 - i;               // uses kb 2s+1
            if (de >= 0 && de <= 4)
                mma_f16(acc[i], fh[de][0], fh[de][1], fh[de][2], fh[de][0], b0, b1);
            if (do_ >= 0 && do_ <= 4)
                mma_f16(acc[i], fh[do_][0], fh[do_][1], fh[do_][2], fh[do_][0], b2, b3);
        }
    }

    // ---- Direct epilogue: streaming stores (y is write-once) ----
    {
        const int j  = 64 * q + (lane >> 2);             // row within tile, block i adds 16i
        const int nn = (lane & 3) * 2;
        float* p0 = yh + (size_t)nn * bstr + t0 + tile * 128 + j;
        #pragma unroll
        for (int i = 0; i < 4; ++i) {
            float* q0 = p0 + i * 16;
            float* q1 = q0 + bstr;
            __stcs(q0,     acc[i][0]);
            __stcs(q1,     acc[i][1]);
            __stcs(q0 + 8, acc[i][2]);
            __stcs(q1 + 8, acc[i][3]);
        }
    }
}

extern "C" void kernel_launch(void* const* d_in, const int* in_sizes, int n_in,
                              void* d_out, int out_size) {
    const float* u = (const float*)d_in[0];   // (8, 512, 4096)
    const float* B = (const float*)d_in[1];   // (512, 64)
    const float* C = (const float*)d_in[2];   // (1, 512, 64)
    const float* D = (const float*)d_in[3];   // (512,)
    float* y = (float*)d_out;                 // (8, 512, 4096)

    dim3 grid(LSEQ / TCTA, HCH);              // (8, 512) = 4096 CTAs
    conv_mma<<<grid, NT>>>(u, B, C, D, y);
}